// round 13
// baseline (speedup 1.0000x reference)
#include <cuda_runtime.h>
#include <cuda_fp16.h>

#define NN 50000
#define EE 800000
#define SC 5
#define NBC 8
#define HC 64
#define NWC 128
#define TBINS 1024
#define RMAXF 5.0f

#define NODE_BLOCKS 196         // 196*256 >= NN

// ---------------- device scratch ----------------
__device__ int g_zb[NN + 16 + NODE_BLOCKS];
__device__ int g_off[NN + 1];
__device__ uint4 g_erec[EE];             // packed CSR edge record: p | sh01 | (spec<<16|sh2) | sender
__device__ __half2 g_feath[NN * 64];     // layer1 feats: (es,ev0),(ev1,ev2)
__device__ float g_res1s[NN * 32];
__device__ __half2 g_tab0h[TBINS * 32];  // layer0 LUT (w1, w3)
__device__ __half2 g_tab1h[TBINS * 32];  // layer1 LUT (w1, w2)
__device__ float g_s0hsl[SC * 32];
__device__ float g_s0res[SC * 64];
__device__ float g_wcomb[32];
// transposed (col-major-in-j) weight copies for vectorized epilogues
__device__ float g_W2sT0[64 * 32];       // [col<64][j<32]  <- w_lin2_s(l=0)[j][col]
__device__ float g_W2vT0[32 * 32];       // [col<32][j<32]  <- w_lin2_v(l=0)[j][col]
__device__ float g_Wl1sT[32 * 32];       // [col<32][j<32]  <- w_lin1_s(l=1)[j][col]
__device__ float g_Wl1vT[32 * 32];       // [col<32][j<32]  <- w_lin1_v(l=1)[j][col]
__device__ float g_WresT[SC * 32 * 32];  // [sp][col<32][j<32] <- w_res_s(l=1)[32+j][sp][col]
__device__ float g_W2sT1[32 * 64];       // [col<32][j<64]  <- w_lin2_s(l=1)[j][col]

__device__ __forceinline__ float silu(float x) { return x / (1.0f + __expf(-x)); }

// ---------------- hist: receiver degrees ----------------
__global__ void k_hist(const float* __restrict__ evec, const int* __restrict__ recv) {
    int e = blockIdx.x * blockDim.x + threadIdx.x;
    if (e >= EE) return;
    float x = evec[e * 3], y = evec[e * 3 + 1], z = evec[e * 3 + 2];
    if (x * x + y * y + z * z < RMAXF * RMAXF) atomicAdd(&g_zb[recv[e]], 1);
}

// ---------------- single-pass scan, warp-parallel decoupled lookback ----------------
#define FLAGP 0x40000000u
#define FLAGX 0x80000000u
#define VALM  0x3FFFFFFFu

__global__ void __launch_bounds__(256) k_scan() {
    __shared__ int ws[8];
    __shared__ int s_tot, s_off;
    int b = blockIdx.x, t = threadIdx.x;
    int lane = t & 31, wid = t >> 5;
    int idx = b * 256 + t;
    int v = (idx < NN) ? g_zb[idx] : 0;
    int x = v;
#pragma unroll
    for (int d = 1; d < 32; d <<= 1) {
        int y = __shfl_up_sync(0xffffffffu, x, d);
        if (lane >= d) x += y;
    }
    if (lane == 31) ws[wid] = x;
    __syncthreads();
    if (wid == 0 && lane < 8) {
        int s = ws[lane];
#pragma unroll
        for (int d = 1; d < 8; d <<= 1) {
            int y = __shfl_up_sync(0xffu, s, d);
            if (lane >= d) s += y;
        }
        ws[lane] = s;
    }
    __syncthreads();
    int incl = x + (wid > 0 ? ws[wid - 1] : 0);
    if (t == 255) s_tot = incl;
    __syncthreads();
    unsigned int* look = reinterpret_cast<unsigned int*>(&g_zb[NN + 16]);
    if (wid == 0) {
        if (b == 0) {
            if (lane == 0) {
                s_off = 0;
                atomicExch(&look[0], (unsigned)s_tot | FLAGX);
            }
        } else {
            if (lane == 0) atomicExch(&look[b], (unsigned)s_tot | FLAGP);
            int run = 0, j = b;
            while (true) {
                int pidx = j - 1 - lane;
                unsigned st = FLAGX;
                if (pidx >= 0) {
                    while ((((st = atomicAdd(&look[pidx], 0u))) & (FLAGP | FLAGX)) == 0u)
                        __nanosleep(32);
                }
                unsigned xmask = __ballot_sync(0xffffffffu, (st & FLAGX) != 0u);
                int val = (int)(st & VALM);
                if (xmask) {
                    int firstx = __ffs(xmask) - 1;
                    int contrib = (lane <= firstx) ? val : 0;
#pragma unroll
                    for (int d = 16; d > 0; d >>= 1)
                        contrib += __shfl_xor_sync(0xffffffffu, contrib, d);
                    run += contrib;
                    break;
                } else {
                    int contrib = val;
#pragma unroll
                    for (int d = 16; d > 0; d >>= 1)
                        contrib += __shfl_xor_sync(0xffffffffu, contrib, d);
                    run += contrib;
                    j -= 32;
                }
            }
            if (lane == 0) {
                s_off = run;
                atomicExch(&look[b], (unsigned)(run + s_tot) | FLAGX);
            }
        }
        if (b == NODE_BLOCKS - 1 && lane == 0) g_off[NN] = s_off + s_tot;
    }
    __syncthreads();
    if (idx < NN) {
        int o = incl - v + s_off;
        g_off[idx] = o;
        g_zb[idx] = o;   // cursor for scatter
    }
}

// ---------------- scatter: packed 16B record ----------------
__global__ void k_scatter(const float* __restrict__ evec, const int* __restrict__ senders,
                          const int* __restrict__ recv, const int* __restrict__ species) {
    int e = blockIdx.x * blockDim.x + threadIdx.x;
    if (e >= EE) return;
    float x = evec[e * 3], y = evec[e * 3 + 1], z = evec[e * 3 + 2];
    float r2 = x * x + y * y + z * z;
    if (r2 >= RMAXF * RMAXF) return;
    float r = sqrtf(r2 + 1e-12f);
    float ir = 1.0f / r;
    const float SQ3 = 1.7320508075688772f;
    int s = senders[e];
    int pos = atomicAdd(&g_zb[recv[e]], 1);
    uint4 rec;
    rec.x = __float_as_uint(r * ((float)(TBINS - 1) / RMAXF));
    __half2 h01 = __floats2half2_rn(SQ3 * x * ir, SQ3 * y * ir);
    rec.y = *reinterpret_cast<unsigned int*>(&h01);
    __half h2 = __float2half_rn(SQ3 * z * ir);
    rec.z = ((unsigned int)species[s] << 16) | (unsigned int)__half_as_ushort(h2);
    rec.w = (unsigned int)s;
    g_erec[pos] = rec;
}

// ---------------- radial-MLP LUT (fp16 rows, both layers) ----------------
__global__ void k_build_table(const float* __restrict__ mlp_w0,
                              const float* __restrict__ mlp_w1,
                              const float* __restrict__ mlp_w2) {
    __shared__ float a1[HC];
    __shared__ float a2[HC];
    __shared__ float eemb[NBC];
    __shared__ float sacc[128];
    int bin = blockIdx.x;
    int l = blockIdx.y;
    int tid = threadIdx.x;
    const float* w0 = mlp_w0 + l * NBC * HC;
    const float* w1 = mlp_w1 + l * HC * HC;
    const float* w2 = mlp_w2 + l * HC * NWC;
    if (tid < NBC) {
        float r = (float)bin * (RMAXF / (float)(TBINS - 1));
        float rs = fmaxf(r, 1e-6f);
        float ir = 1.0f / rs;
        float xr = rs * (1.0f / RMAXF);
        float x3 = xr * xr * xr, x6 = x3 * x3, x7 = x6 * xr, x8 = x7 * xr;
        float env = 1.0f - 28.0f * x6 + 48.0f * x7 - 21.0f * x8;
        const float PI_ = 3.14159265358979323846f;
        eemb[tid] = 0.6324555320336759f * ir * env * sinf(PI_ * xr * (float)(tid + 1));
    }
    __syncthreads();
    if (tid < HC) {
        float acc = 0.f;
#pragma unroll
        for (int k = 0; k < NBC; k++) acc += eemb[k] * w0[k * HC + tid];
        a1[tid] = silu(acc * 0.35355339059327373f);
    }
    __syncthreads();
    if (tid < HC) {
        float acc = 0.f;
#pragma unroll 8
        for (int k = 0; k < HC; k++) acc += a1[k] * w1[k * HC + tid];
        a2[tid] = silu(acc * 0.125f);
    }
    __syncthreads();
    {
        float acc = 0.f;
#pragma unroll 8
        for (int k = 0; k < HC; k++) acc += a2[k] * w2[k * NWC + tid];
        sacc[tid] = acc;
    }
    __syncthreads();
    if (tid < 32) {
        if (l == 0)
            g_tab0h[bin * 32 + tid] = __floats2half2_rn(sacc[tid], sacc[64 + tid]);
        else
            g_tab1h[bin * 32 + tid] = __floats2half2_rn(sacc[tid], sacc[32 + tid]);
    }
}

// ---------------- species-pure prep + wcomb ----------------
__global__ void k_spec0(const float* __restrict__ embed_w,
                        const float* __restrict__ w_lin1_s,
                        const float* __restrict__ w_res_s,
                        const float* __restrict__ w_out1,
                        const float* __restrict__ w_out2) {
    int w = threadIdx.x >> 5, lane = threadIdx.x & 31;
    if (w < SC) {
        float a_hs = 0.f, a_rs0 = 0.f, a_rs1 = 0.f;
#pragma unroll 4
        for (int u = 0; u < 32; u++) {
            float x = embed_w[w * 32 + u] * 0.4472135954999579f;
            a_hs += x * w_lin1_s[u * 32 + lane];
            const float* rs = w_res_s + (size_t)(u * SC + w) * 64;
            a_rs0 += x * rs[lane];
            a_rs1 += x * rs[32 + lane];
        }
        g_s0hsl[w * 32 + lane] = a_hs * 0.17677669529663687f;
        g_s0res[w * 64 + lane] = a_rs0 * 0.07905694150420949f;
        g_s0res[w * 64 + 32 + lane] = a_rs1 * 0.07905694150420949f;
    } else if (w == SC) {
        float acc = 0.f;
#pragma unroll
        for (int k = 0; k < 16; k++) acc += w_out1[lane * 16 + k] * w_out2[k];
        g_wcomb[lane] = acc;
    }
}

// ---------------- transposed weight prep (side stream) ----------------
__global__ void k_wprep(const float* __restrict__ w_lin2_s,
                        const float* __restrict__ w_lin2_v,
                        const float* __restrict__ w_lin1_s,
                        const float* __restrict__ w_lin1_v,
                        const float* __restrict__ w_res_s) {
    int t = blockIdx.x * blockDim.x + threadIdx.x;
    if (t < 1024) {
        int col = t >> 5, j = t & 31;
        g_W2vT0[col * 32 + j] = w_lin2_v[j * 32 + col];
        g_Wl1sT[col * 32 + j] = w_lin1_s[1024 + j * 32 + col];
        g_Wl1vT[col * 32 + j] = w_lin1_v[1024 + j * 32 + col];
    }
    if (t < 2048) {
        int col = t >> 5, j = t & 31;          // col<64, j<32
        g_W2sT0[col * 32 + j] = w_lin2_s[j * 64 + col];
        int c2 = t >> 6, j2 = t & 63;          // c2<32, j2<64
        g_W2sT1[c2 * 64 + j2] = w_lin2_s[4096 + j2 * 64 + c2];
    }
    if (t < 5120) {
        int sp = t >> 10, r = t & 1023;
        int col = r >> 5, j = r & 31;
        g_WresT[sp * 1024 + col * 32 + j] = w_res_s[(size_t)((32 + j) * SC + sp) * 64 + col];
    }
}

// ---------------- fused layer0: gather + vectorized lin2/gate/lin1/res1 ----------------
__global__ void __launch_bounds__(128) k_gfused0(const int* __restrict__ species) {
    __shared__ float sx[4][4][32];
    int w = threadIdx.x >> 5;
    int n = (blockIdx.x * blockDim.x + threadIdx.x) >> 5;
    int lane = threadIdx.x & 31;
    if (n >= NN) return;
    float sr[SC];
#pragma unroll
    for (int s = 0; s < SC; s++) sr[s] = g_s0hsl[s * 32 + lane];
    int e = g_off[n], end = g_off[n + 1];
    float a0 = 0.f, c3x = 0.f, c3y = 0.f, c3z = 0.f;
    for (; e + 3 < end; e += 4) {
        uint4 r[4];
#pragma unroll
        for (int k = 0; k < 4; k++) r[k] = __ldcs(&g_erec[e + k]);
#pragma unroll
        for (int k = 0; k < 4; k++) {
            float p = __uint_as_float(r[k].x);
            int i = (int)p;
            float f = p - (float)i;
            float2 t0 = __half22float2(g_tab0h[i * 32 + lane]);
            float2 t1 = __half22float2(g_tab0h[(i + 1) * 32 + lane]);
            float2 sh = __half22float2(*reinterpret_cast<const __half2*>(&r[k].y));
            float sh2 = __half2float(__ushort_as_half((unsigned short)(r[k].z & 0xffffu)));
            int sp = r[k].z >> 16;
            float es = sr[0];
            es = (sp == 1) ? sr[1] : es;
            es = (sp == 2) ? sr[2] : es;
            es = (sp == 3) ? sr[3] : es;
            es = (sp == 4) ? sr[4] : es;
            float w1 = fmaf(f, t1.x - t0.x, t0.x);
            float w3 = fmaf(f, t1.y - t0.y, t0.y);
            a0 += w1 * es;
            float wv = w3 * es;
            c3x += wv * sh.x; c3y += wv * sh.y; c3z += wv * sh2;
        }
    }
    for (; e < end; e++) {
        uint4 rA = __ldcs(&g_erec[e]);
        float p = __uint_as_float(rA.x);
        int i = (int)p;
        float f = p - (float)i;
        float2 t0 = __half22float2(g_tab0h[i * 32 + lane]);
        float2 t1 = __half22float2(g_tab0h[(i + 1) * 32 + lane]);
        float2 sh = __half22float2(*reinterpret_cast<const __half2*>(&rA.y));
        float sh2 = __half2float(__ushort_as_half((unsigned short)(rA.z & 0xffffu)));
        int sp = rA.z >> 16;
        float es = sr[0];
        es = (sp == 1) ? sr[1] : es;
        es = (sp == 2) ? sr[2] : es;
        es = (sp == 3) ? sr[3] : es;
        es = (sp == 4) ? sr[4] : es;
        float w1 = fmaf(f, t1.x - t0.x, t0.x);
        float w3 = fmaf(f, t1.y - t0.y, t0.y);
        a0 += w1 * es;
        float wv = w3 * es;
        c3x += wv * sh.x; c3y += wv * sh.y; c3z += wv * sh2;
    }
    // ---- vectorized lin2 + residual + gate ----
    sx[w][0][lane] = a0; sx[w][1][lane] = c3x; sx[w][2][lane] = c3y; sx[w][3][lane] = c3z;
    __syncwarp();
    float s0 = 0.f, s1 = 0.f, v0 = 0.f, v1 = 0.f, v2 = 0.f;
#pragma unroll
    for (int jc = 0; jc < 8; jc++) {
        float4 xa = *reinterpret_cast<const float4*>(&sx[w][0][jc * 4]);
        float4 x0 = *reinterpret_cast<const float4*>(&sx[w][1][jc * 4]);
        float4 x1 = *reinterpret_cast<const float4*>(&sx[w][2][jc * 4]);
        float4 x2 = *reinterpret_cast<const float4*>(&sx[w][3][jc * 4]);
        float4 wa = *reinterpret_cast<const float4*>(&g_W2sT0[lane * 32 + jc * 4]);
        float4 wb = *reinterpret_cast<const float4*>(&g_W2sT0[(lane + 32) * 32 + jc * 4]);
        float4 wc = *reinterpret_cast<const float4*>(&g_W2vT0[lane * 32 + jc * 4]);
        s0 += xa.x * wa.x + xa.y * wa.y + xa.z * wa.z + xa.w * wa.w;
        s1 += xa.x * wb.x + xa.y * wb.y + xa.z * wb.z + xa.w * wb.w;
        v0 += x0.x * wc.x + x0.y * wc.y + x0.z * wc.z + x0.w * wc.w;
        v1 += x1.x * wc.x + x1.y * wc.y + x1.z * wc.z + x1.w * wc.w;
        v2 += x2.x * wc.x + x2.y * wc.y + x2.z * wc.z + x2.w * wc.w;
    }
    const float SC_ = 0.0078125f;
    int sp = species[n];
    float hs = silu(s0 * SC_ + g_s0res[sp * 64 + lane]);
    float gate = silu(s1 * SC_ + g_s0res[sp * 64 + 32 + lane]);
    float hv0 = v0 * SC_ * gate;
    float hv1 = v1 * SC_ * gate;
    float hv2 = v2 * SC_ * gate;
    // ---- vectorized layer1 prep: lin1 + residual ----
    __syncwarp();
    sx[w][0][lane] = hs; sx[w][1][lane] = hv0; sx[w][2][lane] = hv1; sx[w][3][lane] = hv2;
    __syncwarp();
    float a_hs = 0.f, a_rs0 = 0.f, ahv0 = 0.f, ahv1 = 0.f, ahv2 = 0.f;
    const float* wres = g_WresT + sp * 1024 + lane * 32;
#pragma unroll
    for (int jc = 0; jc < 8; jc++) {
        float4 xs = *reinterpret_cast<const float4*>(&sx[w][0][jc * 4]);
        float4 x0 = *reinterpret_cast<const float4*>(&sx[w][1][jc * 4]);
        float4 x1 = *reinterpret_cast<const float4*>(&sx[w][2][jc * 4]);
        float4 x2 = *reinterpret_cast<const float4*>(&sx[w][3][jc * 4]);
        float4 ws = *reinterpret_cast<const float4*>(&g_Wl1sT[lane * 32 + jc * 4]);
        float4 wv = *reinterpret_cast<const float4*>(&g_Wl1vT[lane * 32 + jc * 4]);
        float4 wr = *reinterpret_cast<const float4*>(&wres[jc * 4]);
        a_hs += xs.x * ws.x + xs.y * ws.y + xs.z * ws.z + xs.w * ws.w;
        a_rs0 += xs.x * wr.x + xs.y * wr.y + xs.z * wr.z + xs.w * wr.w;
        ahv0 += x0.x * wv.x + x0.y * wv.y + x0.z * wv.z + x0.w * wv.w;
        ahv1 += x1.x * wv.x + x1.y * wv.y + x1.z * wv.z + x1.w * wv.w;
        ahv2 += x2.x * wv.x + x2.y * wv.y + x2.z * wv.z + x2.w * wv.w;
    }
    const float IS32 = 0.17677669529663687f;
    const float IS160 = 0.07905694150420949f;
    g_feath[n * 64 + lane * 2] = __floats2half2_rn(a_hs * IS32, ahv0 * IS32);
    g_feath[n * 64 + lane * 2 + 1] = __floats2half2_rn(ahv1 * IS32, ahv2 * IS32);
    g_res1s[n * 32 + lane] = a_rs0 * IS160;
}

// ---------------- fused layer1: gather + vectorized lin2 + residual + readout ----------------
__global__ void __launch_bounds__(128) k_gfused1(float* __restrict__ out) {
    __shared__ float sx[4][64];
    int w = threadIdx.x >> 5;
    int n = (blockIdx.x * blockDim.x + threadIdx.x) >> 5;
    int lane = threadIdx.x & 31;
    if (n >= NN) return;
    int e = g_off[n], end = g_off[n + 1];
    float a0 = 0.f, a1 = 0.f;
    for (; e + 3 < end; e += 4) {
        uint4 r[4];
        uint2 fw[4];
#pragma unroll
        for (int k = 0; k < 4; k++) r[k] = __ldcs(&g_erec[e + k]);
#pragma unroll
        for (int k = 0; k < 4; k++)
            fw[k] = __ldcs(reinterpret_cast<const uint2*>(&g_feath[(int)r[k].w * 64 + lane * 2]));
#pragma unroll
        for (int k = 0; k < 4; k++) {
            float p = __uint_as_float(r[k].x);
            int i = (int)p;
            float f = p - (float)i;
            float2 t0 = __half22float2(g_tab1h[i * 32 + lane]);
            float2 t1 = __half22float2(g_tab1h[(i + 1) * 32 + lane]);
            float2 f0 = __half22float2(*reinterpret_cast<const __half2*>(&fw[k].x));
            float2 f1 = __half22float2(*reinterpret_cast<const __half2*>(&fw[k].y));
            float2 sh = __half22float2(*reinterpret_cast<const __half2*>(&r[k].y));
            float sh2 = __half2float(__ushort_as_half((unsigned short)(r[k].z & 0xffffu)));
            float w1 = fmaf(f, t1.x - t0.x, t0.x);
            float w2 = fmaf(f, t1.y - t0.y, t0.y);
            a0 += w1 * f0.x;
            a1 += w2 * (f0.y * sh.x + f1.x * sh.y + f1.y * sh2);
        }
    }
    for (; e < end; e++) {
        uint4 rA = __ldcs(&g_erec[e]);
        float p = __uint_as_float(rA.x);
        int i = (int)p;
        float f = p - (float)i;
        float2 t0 = __half22float2(g_tab1h[i * 32 + lane]);
        float2 t1 = __half22float2(g_tab1h[(i + 1) * 32 + lane]);
        uint2 fwA = __ldcs(reinterpret_cast<const uint2*>(&g_feath[(int)rA.w * 64 + lane * 2]));
        float2 f0 = __half22float2(*reinterpret_cast<const __half2*>(&fwA.x));
        float2 f1 = __half22float2(*reinterpret_cast<const __half2*>(&fwA.y));
        float2 sh = __half22float2(*reinterpret_cast<const __half2*>(&rA.y));
        float sh2 = __half2float(__ushort_as_half((unsigned short)(rA.z & 0xffffu)));
        float w1 = fmaf(f, t1.x - t0.x, t0.x);
        float w2 = fmaf(f, t1.y - t0.y, t0.y);
        a0 += w1 * f0.x;
        a1 += w2 * (f0.y * sh.x + f1.x * sh.y + f1.y * sh2);
    }
    // ---- vectorized lin2 (scalar half) + residual + readout ----
    sx[w][lane] = a0;
    sx[w][32 + lane] = a1 * 0.5773502691896258f;
    __syncwarp();
    float s0 = 0.f;
#pragma unroll
    for (int jc = 0; jc < 16; jc++) {
        float4 xv = *reinterpret_cast<const float4*>(&sx[w][jc * 4]);
        float4 wv = *reinterpret_cast<const float4*>(&g_W2sT1[lane * 64 + jc * 4]);
        s0 += xv.x * wv.x + xv.y * wv.y + xv.z * wv.z + xv.w * wv.w;
    }
    const float SC_ = 0.0078125f;
    float hs = silu(s0 * SC_ + g_res1s[n * 32 + lane]);
    float z = hs * g_wcomb[lane];
    z += __shfl_xor_sync(0xffffffffu, z, 16);
    z += __shfl_xor_sync(0xffffffffu, z, 8);
    z += __shfl_xor_sync(0xffffffffu, z, 4);
    z += __shfl_xor_sync(0xffffffffu, z, 2);
    z += __shfl_xor_sync(0xffffffffu, z, 1);
    if (lane == 0) out[n] = z * (0.17677669529663687f * 0.25f);
}

// ---------------- launch ----------------
extern "C" void kernel_launch(void* const* d_in, const int* in_sizes, int n_in,
                              void* d_out, int out_size) {
    const float* edge_vectors = (const float*)d_in[0];
    const int* species        = (const int*)d_in[1];
    const int* senders        = (const int*)d_in[2];
    const int* receivers      = (const int*)d_in[3];
    const float* embed_w      = (const float*)d_in[4];
    const float* w_res_s      = (const float*)d_in[5];
    const float* w_lin1_s     = (const float*)d_in[7];
    const float* w_lin1_v     = (const float*)d_in[8];
    const float* mlp_w0       = (const float*)d_in[9];
    const float* mlp_w1       = (const float*)d_in[10];
    const float* mlp_w2       = (const float*)d_in[11];
    const float* w_lin2_s     = (const float*)d_in[12];
    const float* w_lin2_v     = (const float*)d_in[13];
    const float* w_out1       = (const float*)d_in[14];
    const float* w_out2       = (const float*)d_in[15];
    float* out = (float*)d_out;

    static cudaStream_t s2 = nullptr;
    static cudaEvent_t evA = nullptr, evB = nullptr;
    if (!s2) {
        cudaStreamCreateWithFlags(&s2, cudaStreamNonBlocking);
        cudaEventCreateWithFlags(&evA, cudaEventDisableTiming);
        cudaEventCreateWithFlags(&evB, cudaEventDisableTiming);
    }

    void* zb_ptr = nullptr;
    cudaGetSymbolAddress(&zb_ptr, g_zb);

    const int EB256 = (EE + 255) / 256;
    const int GPB = (NN + 3) / 4;          // fused gathers: 128-thr blocks, warp per node

    // fork: side stream builds LUT + species-pure prep + transposed weights
    cudaEventRecord(evA, 0);
    cudaStreamWaitEvent(s2, evA, 0);
    k_build_table<<<dim3(TBINS, 2), 128, 0, s2>>>(mlp_w0, mlp_w1, mlp_w2);
    k_spec0<<<1, 192, 0, s2>>>(embed_w, w_lin1_s, w_res_s, w_out1, w_out2);
    k_wprep<<<20, 256, 0, s2>>>(w_lin2_s, w_lin2_v, w_lin1_s, w_lin1_v, w_res_s);
    cudaEventRecord(evB, s2);

    // main chain: CSR build
    cudaMemsetAsync(zb_ptr, 0, (NN + 16 + NODE_BLOCKS) * sizeof(int));
    k_hist<<<EB256, 256>>>(edge_vectors, receivers);
    k_scan<<<NODE_BLOCKS, 256>>>();
    k_scatter<<<EB256, 256>>>(edge_vectors, senders, receivers, species);

    // join, then fused layers
    cudaStreamWaitEvent(0, evB, 0);
    k_gfused0<<<GPB, 128>>>(species);
    k_gfused1<<<GPB, 128>>>(out);
}

// round 15
// speedup vs baseline: 2.7175x; 2.7175x over previous
#include <cuda_runtime.h>
#include <cuda_fp16.h>

#define NN 50000
#define EE 800000
#define SC 5
#define NBC 8
#define HC 64
#define NWC 128
#define TBINS 1024
#define RMAXF 5.0f

#define NODE_BLOCKS 196         // 196*256 >= NN

// ---------------- device scratch ----------------
__device__ int g_zb[NN + 16 + NODE_BLOCKS];
__device__ int g_off[NN + 1];
__device__ uint4 g_erec[EE];             // packed CSR edge record: p | sh01 | (spec<<16|sh2) | sender
__device__ __half2 g_feath[NN * 64];     // layer1 feats: (es,ev0),(ev1,ev2)
__device__ float g_res1s[NN * 32];
__device__ __half2 g_tab0h[TBINS * 32];  // layer0 LUT (w1, w3)
__device__ __half2 g_tab1h[TBINS * 32];  // layer1 LUT (w1, w2)
__device__ float g_s0hsl[SC * 32];
__device__ float g_s0res[SC * 64];
__device__ float g_wcomb[32];

__device__ __forceinline__ float silu(float x) { return x / (1.0f + __expf(-x)); }

// ---------------- hist: receiver degrees ----------------
__global__ void k_hist(const float* __restrict__ evec, const int* __restrict__ recv) {
    int e = blockIdx.x * blockDim.x + threadIdx.x;
    if (e >= EE) return;
    float x = evec[e * 3], y = evec[e * 3 + 1], z = evec[e * 3 + 2];
    if (x * x + y * y + z * z < RMAXF * RMAXF) atomicAdd(&g_zb[recv[e]], 1);
}

// ---------------- single-pass scan, warp-parallel decoupled lookback ----------------
#define FLAGP 0x40000000u
#define FLAGX 0x80000000u
#define VALM  0x3FFFFFFFu

__global__ void __launch_bounds__(256) k_scan() {
    __shared__ int ws[8];
    __shared__ int s_tot, s_off;
    int b = blockIdx.x, t = threadIdx.x;
    int lane = t & 31, wid = t >> 5;
    int idx = b * 256 + t;
    int v = (idx < NN) ? g_zb[idx] : 0;
    int x = v;
#pragma unroll
    for (int d = 1; d < 32; d <<= 1) {
        int y = __shfl_up_sync(0xffffffffu, x, d);
        if (lane >= d) x += y;
    }
    if (lane == 31) ws[wid] = x;
    __syncthreads();
    if (wid == 0 && lane < 8) {
        int s = ws[lane];
#pragma unroll
        for (int d = 1; d < 8; d <<= 1) {
            int y = __shfl_up_sync(0xffu, s, d);
            if (lane >= d) s += y;
        }
        ws[lane] = s;
    }
    __syncthreads();
    int incl = x + (wid > 0 ? ws[wid - 1] : 0);
    if (t == 255) s_tot = incl;
    __syncthreads();
    unsigned int* look = reinterpret_cast<unsigned int*>(&g_zb[NN + 16]);
    if (wid == 0) {
        if (b == 0) {
            if (lane == 0) {
                s_off = 0;
                atomicExch(&look[0], (unsigned)s_tot | FLAGX);
            }
        } else {
            if (lane == 0) atomicExch(&look[b], (unsigned)s_tot | FLAGP);
            int run = 0, j = b;
            while (true) {
                int pidx = j - 1 - lane;
                unsigned st = FLAGX;
                if (pidx >= 0) {
                    while ((((st = atomicAdd(&look[pidx], 0u))) & (FLAGP | FLAGX)) == 0u)
                        __nanosleep(32);
                }
                unsigned xmask = __ballot_sync(0xffffffffu, (st & FLAGX) != 0u);
                int val = (int)(st & VALM);
                if (xmask) {
                    int firstx = __ffs(xmask) - 1;
                    int contrib = (lane <= firstx) ? val : 0;
#pragma unroll
                    for (int d = 16; d > 0; d >>= 1)
                        contrib += __shfl_xor_sync(0xffffffffu, contrib, d);
                    run += contrib;
                    break;
                } else {
                    int contrib = val;
#pragma unroll
                    for (int d = 16; d > 0; d >>= 1)
                        contrib += __shfl_xor_sync(0xffffffffu, contrib, d);
                    run += contrib;
                    j -= 32;
                }
            }
            if (lane == 0) {
                s_off = run;
                atomicExch(&look[b], (unsigned)(run + s_tot) | FLAGX);
            }
        }
        if (b == NODE_BLOCKS - 1 && lane == 0) g_off[NN] = s_off + s_tot;
    }
    __syncthreads();
    if (idx < NN) {
        int o = incl - v + s_off;
        g_off[idx] = o;
        g_zb[idx] = o;   // cursor for scatter
    }
}

// ---------------- scatter: packed 16B record ----------------
__global__ void k_scatter(const float* __restrict__ evec, const int* __restrict__ senders,
                          const int* __restrict__ recv, const int* __restrict__ species) {
    int e = blockIdx.x * blockDim.x + threadIdx.x;
    if (e >= EE) return;
    float x = evec[e * 3], y = evec[e * 3 + 1], z = evec[e * 3 + 2];
    float r2 = x * x + y * y + z * z;
    if (r2 >= RMAXF * RMAXF) return;
    float r = sqrtf(r2 + 1e-12f);
    float ir = 1.0f / r;
    const float SQ3 = 1.7320508075688772f;
    int s = senders[e];
    int pos = atomicAdd(&g_zb[recv[e]], 1);
    uint4 rec;
    rec.x = __float_as_uint(r * ((float)(TBINS - 1) / RMAXF));
    __half2 h01 = __floats2half2_rn(SQ3 * x * ir, SQ3 * y * ir);
    rec.y = *reinterpret_cast<unsigned int*>(&h01);
    __half h2 = __float2half_rn(SQ3 * z * ir);
    rec.z = ((unsigned int)species[s] << 16) | (unsigned int)__half_as_ushort(h2);
    rec.w = (unsigned int)s;
    g_erec[pos] = rec;
}

// ---------------- radial-MLP LUT (fp16 rows, both layers) ----------------
__global__ void k_build_table(const float* __restrict__ mlp_w0,
                              const float* __restrict__ mlp_w1,
                              const float* __restrict__ mlp_w2) {
    __shared__ float a1[HC];
    __shared__ float a2[HC];
    __shared__ float eemb[NBC];
    __shared__ float sacc[128];
    int bin = blockIdx.x;
    int l = blockIdx.y;
    int tid = threadIdx.x;
    const float* w0 = mlp_w0 + l * NBC * HC;
    const float* w1 = mlp_w1 + l * HC * HC;
    const float* w2 = mlp_w2 + l * HC * NWC;
    if (tid < NBC) {
        float r = (float)bin * (RMAXF / (float)(TBINS - 1));
        float rs = fmaxf(r, 1e-6f);
        float ir = 1.0f / rs;
        float xr = rs * (1.0f / RMAXF);
        float x3 = xr * xr * xr, x6 = x3 * x3, x7 = x6 * xr, x8 = x7 * xr;
        float env = 1.0f - 28.0f * x6 + 48.0f * x7 - 21.0f * x8;
        const float PI_ = 3.14159265358979323846f;
        eemb[tid] = 0.6324555320336759f * ir * env * sinf(PI_ * xr * (float)(tid + 1));
    }
    __syncthreads();
    if (tid < HC) {
        float acc = 0.f;
#pragma unroll
        for (int k = 0; k < NBC; k++) acc += eemb[k] * w0[k * HC + tid];
        a1[tid] = silu(acc * 0.35355339059327373f);
    }
    __syncthreads();
    if (tid < HC) {
        float acc = 0.f;
#pragma unroll 8
        for (int k = 0; k < HC; k++) acc += a1[k] * w1[k * HC + tid];
        a2[tid] = silu(acc * 0.125f);
    }
    __syncthreads();
    {
        float acc = 0.f;
#pragma unroll 8
        for (int k = 0; k < HC; k++) acc += a2[k] * w2[k * NWC + tid];
        sacc[tid] = acc;
    }
    __syncthreads();
    if (tid < 32) {
        if (l == 0)
            g_tab0h[bin * 32 + tid] = __floats2half2_rn(sacc[tid], sacc[64 + tid]);
        else
            g_tab1h[bin * 32 + tid] = __floats2half2_rn(sacc[tid], sacc[32 + tid]);
    }
}

// ---------------- species-pure prep + wcomb ----------------
__global__ void k_spec0(const float* __restrict__ embed_w,
                        const float* __restrict__ w_lin1_s,
                        const float* __restrict__ w_res_s,
                        const float* __restrict__ w_out1,
                        const float* __restrict__ w_out2) {
    int w = threadIdx.x >> 5, lane = threadIdx.x & 31;
    if (w < SC) {
        float a_hs = 0.f, a_rs0 = 0.f, a_rs1 = 0.f;
#pragma unroll 4
        for (int u = 0; u < 32; u++) {
            float x = embed_w[w * 32 + u] * 0.4472135954999579f;
            a_hs += x * w_lin1_s[u * 32 + lane];
            const float* rs = w_res_s + (size_t)(u * SC + w) * 64;
            a_rs0 += x * rs[lane];
            a_rs1 += x * rs[32 + lane];
        }
        g_s0hsl[w * 32 + lane] = a_hs * 0.17677669529663687f;
        g_s0res[w * 64 + lane] = a_rs0 * 0.07905694150420949f;
        g_s0res[w * 64 + 32 + lane] = a_rs1 * 0.07905694150420949f;
    } else if (w == SC) {
        float acc = 0.f;
#pragma unroll
        for (int k = 0; k < 16; k++) acc += w_out1[lane * 16 + k] * w_out2[k];
        g_wcomb[lane] = acc;
    }
}

// ---------------- fused layer0: gather + lin2/gate/lin1/res1 (smem-broadcast epilogue) ----------------
__global__ void __launch_bounds__(128) k_gfused0(const int* __restrict__ species,
                                                 const float* __restrict__ w_lin2_s,
                                                 const float* __restrict__ w_lin2_v,
                                                 const float* __restrict__ w_lin1_s,
                                                 const float* __restrict__ w_lin1_v,
                                                 const float* __restrict__ w_res_s) {
    __shared__ float sx[4][4][32];
    int w = threadIdx.x >> 5;
    int n = (blockIdx.x * blockDim.x + threadIdx.x) >> 5;
    int lane = threadIdx.x & 31;
    if (n >= NN) return;
    float sr[SC];
#pragma unroll
    for (int s = 0; s < SC; s++) sr[s] = g_s0hsl[s * 32 + lane];
    int e = g_off[n], end = g_off[n + 1];
    float a0 = 0.f, c3x = 0.f, c3y = 0.f, c3z = 0.f;
    for (; e + 3 < end; e += 4) {
        uint4 r[4];
#pragma unroll
        for (int k = 0; k < 4; k++) r[k] = __ldcs(&g_erec[e + k]);
#pragma unroll
        for (int k = 0; k < 4; k++) {
            float p = __uint_as_float(r[k].x);
            int i = (int)p;
            float f = p - (float)i;
            float2 t0 = __half22float2(g_tab0h[i * 32 + lane]);
            float2 t1 = __half22float2(g_tab0h[(i + 1) * 32 + lane]);
            float2 sh = __half22float2(*reinterpret_cast<const __half2*>(&r[k].y));
            float sh2 = __half2float(__ushort_as_half((unsigned short)(r[k].z & 0xffffu)));
            int sp = r[k].z >> 16;
            float es = sr[0];
            es = (sp == 1) ? sr[1] : es;
            es = (sp == 2) ? sr[2] : es;
            es = (sp == 3) ? sr[3] : es;
            es = (sp == 4) ? sr[4] : es;
            float w1 = fmaf(f, t1.x - t0.x, t0.x);
            float w3 = fmaf(f, t1.y - t0.y, t0.y);
            a0 += w1 * es;
            float wv = w3 * es;
            c3x += wv * sh.x; c3y += wv * sh.y; c3z += wv * sh2;
        }
    }
    for (; e < end; e++) {
        uint4 rA = __ldcs(&g_erec[e]);
        float p = __uint_as_float(rA.x);
        int i = (int)p;
        float f = p - (float)i;
        float2 t0 = __half22float2(g_tab0h[i * 32 + lane]);
        float2 t1 = __half22float2(g_tab0h[(i + 1) * 32 + lane]);
        float2 sh = __half22float2(*reinterpret_cast<const __half2*>(&rA.y));
        float sh2 = __half2float(__ushort_as_half((unsigned short)(rA.z & 0xffffu)));
        int sp = rA.z >> 16;
        float es = sr[0];
        es = (sp == 1) ? sr[1] : es;
        es = (sp == 2) ? sr[2] : es;
        es = (sp == 3) ? sr[3] : es;
        es = (sp == 4) ? sr[4] : es;
        float w1 = fmaf(f, t1.x - t0.x, t0.x);
        float w3 = fmaf(f, t1.y - t0.y, t0.y);
        a0 += w1 * es;
        float wv = w3 * es;
        c3x += wv * sh.x; c3y += wv * sh.y; c3z += wv * sh2;
    }
    // ---- lin2 + residual + gate: smem-broadcast x, coalesced weights ----
    sx[w][0][lane] = a0; sx[w][1][lane] = c3x; sx[w][2][lane] = c3y; sx[w][3][lane] = c3z;
    __syncwarp();
    float s0 = 0.f, s1 = 0.f, v0 = 0.f, v1 = 0.f, v2 = 0.f;
#pragma unroll
    for (int jc = 0; jc < 8; jc++) {
        float4 xa = *reinterpret_cast<const float4*>(&sx[w][0][jc * 4]);
        float4 x0 = *reinterpret_cast<const float4*>(&sx[w][1][jc * 4]);
        float4 x1 = *reinterpret_cast<const float4*>(&sx[w][2][jc * 4]);
        float4 x2 = *reinterpret_cast<const float4*>(&sx[w][3][jc * 4]);
        float xaa[4] = {xa.x, xa.y, xa.z, xa.w};
        float x0a[4] = {x0.x, x0.y, x0.z, x0.w};
        float x1a[4] = {x1.x, x1.y, x1.z, x1.w};
        float x2a[4] = {x2.x, x2.y, x2.z, x2.w};
#pragma unroll
        for (int d = 0; d < 4; d++) {
            int j = jc * 4 + d;
            float wa = w_lin2_s[j * 64 + lane];
            float wb = w_lin2_s[j * 64 + 32 + lane];
            float wc = w_lin2_v[j * 32 + lane];
            s0 += xaa[d] * wa;
            s1 += xaa[d] * wb;
            v0 += x0a[d] * wc; v1 += x1a[d] * wc; v2 += x2a[d] * wc;
        }
    }
    const float SC_ = 0.0078125f;
    int sp = species[n];
    float hs = silu(s0 * SC_ + g_s0res[sp * 64 + lane]);
    float gate = silu(s1 * SC_ + g_s0res[sp * 64 + 32 + lane]);
    float hv0 = v0 * SC_ * gate;
    float hv1 = v1 * SC_ * gate;
    float hv2 = v2 * SC_ * gate;
    // ---- layer1 prep: lin1 + residual ----
    __syncwarp();
    sx[w][0][lane] = hs; sx[w][1][lane] = hv0; sx[w][2][lane] = hv1; sx[w][3][lane] = hv2;
    __syncwarp();
    const float* Wl1s = w_lin1_s + 1024;
    const float* Wl1v = w_lin1_v + 1024;
    float a_hs = 0.f, a_rs0 = 0.f, ahv0 = 0.f, ahv1 = 0.f, ahv2 = 0.f;
#pragma unroll
    for (int jc = 0; jc < 8; jc++) {
        float4 xs = *reinterpret_cast<const float4*>(&sx[w][0][jc * 4]);
        float4 x0 = *reinterpret_cast<const float4*>(&sx[w][1][jc * 4]);
        float4 x1 = *reinterpret_cast<const float4*>(&sx[w][2][jc * 4]);
        float4 x2 = *reinterpret_cast<const float4*>(&sx[w][3][jc * 4]);
        float xsa[4] = {xs.x, xs.y, xs.z, xs.w};
        float x0a[4] = {x0.x, x0.y, x0.z, x0.w};
        float x1a[4] = {x1.x, x1.y, x1.z, x1.w};
        float x2a[4] = {x2.x, x2.y, x2.z, x2.w};
#pragma unroll
        for (int d = 0; d < 4; d++) {
            int j = jc * 4 + d;
            float ws = Wl1s[j * 32 + lane];
            float wv = Wl1v[j * 32 + lane];
            float wr = w_res_s[(size_t)(((32 + j) * SC) + sp) * 64 + lane];
            a_hs += xsa[d] * ws;
            a_rs0 += xsa[d] * wr;
            ahv0 += x0a[d] * wv; ahv1 += x1a[d] * wv; ahv2 += x2a[d] * wv;
        }
    }
    const float IS32 = 0.17677669529663687f;
    const float IS160 = 0.07905694150420949f;
    g_feath[n * 64 + lane * 2] = __floats2half2_rn(a_hs * IS32, ahv0 * IS32);
    g_feath[n * 64 + lane * 2 + 1] = __floats2half2_rn(ahv1 * IS32, ahv2 * IS32);
    g_res1s[n * 32 + lane] = a_rs0 * IS160;
}

// ---------------- fused layer1: gather + lin2 + residual + readout ----------------
__global__ void __launch_bounds__(128) k_gfused1(const float* __restrict__ w_lin2_s,
                                                 float* __restrict__ out) {
    __shared__ float sx[4][64];
    int w = threadIdx.x >> 5;
    int n = (blockIdx.x * blockDim.x + threadIdx.x) >> 5;
    int lane = threadIdx.x & 31;
    if (n >= NN) return;
    int e = g_off[n], end = g_off[n + 1];
    float a0 = 0.f, a1 = 0.f;
    for (; e + 3 < end; e += 4) {
        uint4 r[4];
        uint2 fw[4];
#pragma unroll
        for (int k = 0; k < 4; k++) r[k] = __ldcs(&g_erec[e + k]);
#pragma unroll
        for (int k = 0; k < 4; k++)
            fw[k] = __ldcs(reinterpret_cast<const uint2*>(&g_feath[(int)r[k].w * 64 + lane * 2]));
#pragma unroll
        for (int k = 0; k < 4; k++) {
            float p = __uint_as_float(r[k].x);
            int i = (int)p;
            float f = p - (float)i;
            float2 t0 = __half22float2(g_tab1h[i * 32 + lane]);
            float2 t1 = __half22float2(g_tab1h[(i + 1) * 32 + lane]);
            float2 f0 = __half22float2(*reinterpret_cast<const __half2*>(&fw[k].x));
            float2 f1 = __half22float2(*reinterpret_cast<const __half2*>(&fw[k].y));
            float2 sh = __half22float2(*reinterpret_cast<const __half2*>(&r[k].y));
            float sh2 = __half2float(__ushort_as_half((unsigned short)(r[k].z & 0xffffu)));
            float w1 = fmaf(f, t1.x - t0.x, t0.x);
            float w2 = fmaf(f, t1.y - t0.y, t0.y);
            a0 += w1 * f0.x;
            a1 += w2 * (f0.y * sh.x + f1.x * sh.y + f1.y * sh2);
        }
    }
    for (; e < end; e++) {
        uint4 rA = __ldcs(&g_erec[e]);
        float p = __uint_as_float(rA.x);
        int i = (int)p;
        float f = p - (float)i;
        float2 t0 = __half22float2(g_tab1h[i * 32 + lane]);
        float2 t1 = __half22float2(g_tab1h[(i + 1) * 32 + lane]);
        uint2 fwA = __ldcs(reinterpret_cast<const uint2*>(&g_feath[(int)rA.w * 64 + lane * 2]));
        float2 f0 = __half22float2(*reinterpret_cast<const __half2*>(&fwA.x));
        float2 f1 = __half22float2(*reinterpret_cast<const __half2*>(&fwA.y));
        float2 sh = __half22float2(*reinterpret_cast<const __half2*>(&rA.y));
        float sh2 = __half2float(__ushort_as_half((unsigned short)(rA.z & 0xffffu)));
        float w1 = fmaf(f, t1.x - t0.x, t0.x);
        float w2 = fmaf(f, t1.y - t0.y, t0.y);
        a0 += w1 * f0.x;
        a1 += w2 * (f0.y * sh.x + f1.x * sh.y + f1.y * sh2);
    }
    // ---- lin2 (scalar half) + residual + readout: smem-broadcast x ----
    sx[w][lane] = a0;
    sx[w][32 + lane] = a1 * 0.5773502691896258f;
    __syncwarp();
    const float* W2s = w_lin2_s + 4096;  // l=1
    float s0 = 0.f;
#pragma unroll
    for (int jc = 0; jc < 16; jc++) {
        float4 xv = *reinterpret_cast<const float4*>(&sx[w][jc * 4]);
        float xa[4] = {xv.x, xv.y, xv.z, xv.w};
#pragma unroll
        for (int d = 0; d < 4; d++) {
            int j = jc * 4 + d;
            s0 += xa[d] * W2s[j * 64 + lane];
        }
    }
    const float SC_ = 0.0078125f;
    float hs = silu(s0 * SC_ + g_res1s[n * 32 + lane]);
    float z = hs * g_wcomb[lane];
    z += __shfl_xor_sync(0xffffffffu, z, 16);
    z += __shfl_xor_sync(0xffffffffu, z, 8);
    z += __shfl_xor_sync(0xffffffffu, z, 4);
    z += __shfl_xor_sync(0xffffffffu, z, 2);
    z += __shfl_xor_sync(0xffffffffu, z, 1);
    if (lane == 0) out[n] = z * (0.17677669529663687f * 0.25f);
}

// ---------------- launch ----------------
extern "C" void kernel_launch(void* const* d_in, const int* in_sizes, int n_in,
                              void* d_out, int out_size) {
    const float* edge_vectors = (const float*)d_in[0];
    const int* species        = (const int*)d_in[1];
    const int* senders        = (const int*)d_in[2];
    const int* receivers      = (const int*)d_in[3];
    const float* embed_w      = (const float*)d_in[4];
    const float* w_res_s      = (const float*)d_in[5];
    const float* w_lin1_s     = (const float*)d_in[7];
    const float* w_lin1_v     = (const float*)d_in[8];
    const float* mlp_w0       = (const float*)d_in[9];
    const float* mlp_w1       = (const float*)d_in[10];
    const float* mlp_w2       = (const float*)d_in[11];
    const float* w_lin2_s     = (const float*)d_in[12];
    const float* w_lin2_v     = (const float*)d_in[13];
    const float* w_out1       = (const float*)d_in[14];
    const float* w_out2       = (const float*)d_in[15];
    float* out = (float*)d_out;

    static cudaStream_t s2 = nullptr;
    static cudaEvent_t evA = nullptr, evB = nullptr;
    if (!s2) {
        cudaStreamCreateWithFlags(&s2, cudaStreamNonBlocking);
        cudaEventCreateWithFlags(&evA, cudaEventDisableTiming);
        cudaEventCreateWithFlags(&evB, cudaEventDisableTiming);
    }

    void* zb_ptr = nullptr;
    cudaGetSymbolAddress(&zb_ptr, g_zb);

    const int EB256 = (EE + 255) / 256;
    const int GPB = (NN + 3) / 4;          // fused gathers: 128-thr blocks, warp per node

    // fork: side stream builds LUT + species-pure prep
    cudaEventRecord(evA, 0);
    cudaStreamWaitEvent(s2, evA, 0);
    k_build_table<<<dim3(TBINS, 2), 128, 0, s2>>>(mlp_w0, mlp_w1, mlp_w2);
    k_spec0<<<1, 192, 0, s2>>>(embed_w, w_lin1_s, w_res_s, w_out1, w_out2);
    cudaEventRecord(evB, s2);

    // main chain: CSR build
    cudaMemsetAsync(zb_ptr, 0, (NN + 16 + NODE_BLOCKS) * sizeof(int));
    k_hist<<<EB256, 256>>>(edge_vectors, receivers);
    k_scan<<<NODE_BLOCKS, 256>>>();
    k_scatter<<<EB256, 256>>>(edge_vectors, senders, receivers, species);

    // join, then fused layers
    cudaStreamWaitEvent(0, evB, 0);
    k_gfused0<<<GPB, 128>>>(species, w_lin2_s, w_lin2_v, w_lin1_s, w_lin1_v, w_res_s);
    k_gfused1<<<GPB, 128>>>(w_lin2_s, out);
}